// round 1
// baseline (speedup 1.0000x reference)
#include <cuda_runtime.h>

// ---------------------------------------------------------------------------
// SiameseBrainNet: 2x (3-layer GCN + mean pool) + pairwise distance
// N=20000 nodes, E=640000 edges, D=H=512, G=64 graphs
// ---------------------------------------------------------------------------

#define NN 20000
#define EE 640000
#define DH 512
#define GG 64

// ---- scratch (device globals; no allocation allowed) ----------------------
__device__ float g_gemm[NN * DH];     // GEMM output (h = x @ W)
__device__ float g_x[NN * DH];        // aggregation output / next layer input
__device__ int   g_deg[NN];
__device__ int   g_rowptr[NN + 1];
__device__ int   g_cursor[NN];
__device__ float g_dinv[NN];
__device__ int   g_csr_src[EE];
__device__ float g_csr_norm[EE];
__device__ float g_pooled[2][GG * DH];

// ---------------------------------------------------------------------------
// CSR construction
// ---------------------------------------------------------------------------
__global__ void zero_deg_kernel() {
    int i = blockIdx.x * blockDim.x + threadIdx.x;
    if (i < NN) g_deg[i] = 0;
}

__global__ void count_deg_kernel(const int* __restrict__ dst) {
    int e = blockIdx.x * blockDim.x + threadIdx.x;
    if (e < EE) atomicAdd(&g_deg[dst[e]], 1);
}

__global__ void dinv_kernel() {
    int i = blockIdx.x * blockDim.x + threadIdx.x;
    if (i < NN) g_dinv[i] = rsqrtf((float)g_deg[i] + 1.0f);
}

// single-block exclusive scan of g_deg -> g_rowptr (and cursor copy)
__global__ void scan_kernel() {
    __shared__ int sh[1024];
    int tid = threadIdx.x;
    const int chunk = (NN + 1023) / 1024;   // 20
    int base = tid * chunk;
    int local = 0;
    for (int j = 0; j < chunk; j++) {
        int idx = base + j;
        if (idx < NN) local += g_deg[idx];
    }
    sh[tid] = local;
    __syncthreads();
    for (int off = 1; off < 1024; off <<= 1) {
        int v = (tid >= off) ? sh[tid - off] : 0;
        __syncthreads();
        sh[tid] += v;
        __syncthreads();
    }
    int run = (tid == 0) ? 0 : sh[tid - 1];
    for (int j = 0; j < chunk; j++) {
        int idx = base + j;
        if (idx < NN) {
            g_rowptr[idx] = run;
            g_cursor[idx] = run;
            run += g_deg[idx];
        }
    }
    if (tid == 1023) g_rowptr[NN] = sh[1023];
}

__global__ void fill_csr_kernel(const int* __restrict__ src, const int* __restrict__ dst) {
    int e = blockIdx.x * blockDim.x + threadIdx.x;
    if (e < EE) {
        int s = src[e];
        int d = dst[e];
        int pos = atomicAdd(&g_cursor[d], 1);
        g_csr_src[pos]  = s;
        g_csr_norm[pos] = g_dinv[s] * g_dinv[d];
    }
}

// ---------------------------------------------------------------------------
// SGEMM: C[M,512] = A[M,512] @ B[512,512]
// 128x128 block tile, BK=8, 256 threads, 8x8 per thread (split 4+4 @ +64)
// ---------------------------------------------------------------------------
__global__ __launch_bounds__(256) void sgemm_kernel(const float* __restrict__ A,
                                                    const float* __restrict__ B,
                                                    float* __restrict__ C, int M) {
    const int K = DH, NCOL = DH;
    __shared__ float As[8][128];
    __shared__ float Bs[8][128];

    int tid = threadIdx.x;
    int bm = blockIdx.y, bn = blockIdx.x;

    int rowA = tid >> 1;            // 0..127
    int colA = (tid & 1) * 4;       // 0 or 4
    int rowB = tid >> 5;            // 0..7
    int colB = (tid & 31) * 4;      // 0..124
    int tx = tid & 15, ty = tid >> 4;

    int aRowG = bm * 128 + rowA;
    const float* Bbase = B + bn * 128;

    float acc[8][8];
#pragma unroll
    for (int i = 0; i < 8; i++)
#pragma unroll
        for (int j = 0; j < 8; j++) acc[i][j] = 0.0f;

    for (int k0 = 0; k0 < K; k0 += 8) {
        float4 a = (aRowG < M) ? *(const float4*)&A[(size_t)aRowG * K + k0 + colA]
                               : make_float4(0.f, 0.f, 0.f, 0.f);
        As[colA + 0][rowA] = a.x;
        As[colA + 1][rowA] = a.y;
        As[colA + 2][rowA] = a.z;
        As[colA + 3][rowA] = a.w;
        float4 bv = *(const float4*)&Bbase[(size_t)(k0 + rowB) * NCOL + colB];
        *(float4*)&Bs[rowB][colB] = bv;
        __syncthreads();

#pragma unroll
        for (int kk = 0; kk < 8; kk++) {
            float ra[8], rb[8];
            *(float4*)&ra[0] = *(const float4*)&As[kk][ty * 4];
            *(float4*)&ra[4] = *(const float4*)&As[kk][ty * 4 + 64];
            *(float4*)&rb[0] = *(const float4*)&Bs[kk][tx * 4];
            *(float4*)&rb[4] = *(const float4*)&Bs[kk][tx * 4 + 64];
#pragma unroll
            for (int i = 0; i < 8; i++)
#pragma unroll
                for (int j = 0; j < 8; j++) acc[i][j] += ra[i] * rb[j];
        }
        __syncthreads();
    }

#pragma unroll
    for (int i = 0; i < 8; i++) {
        int row = bm * 128 + ((i < 4) ? (ty * 4 + i) : (64 + ty * 4 + (i - 4)));
        if (row < M) {
            float* cp = &C[(size_t)row * NCOL + bn * 128];
            *(float4*)&cp[tx * 4]      = make_float4(acc[i][0], acc[i][1], acc[i][2], acc[i][3]);
            *(float4*)&cp[tx * 4 + 64] = make_float4(acc[i][4], acc[i][5], acc[i][6], acc[i][7]);
        }
    }
}

// ---------------------------------------------------------------------------
// Aggregation: out[i] = sum_{e: dst==i} norm_e * h[src_e] + h[i]*dinv[i]^2 + b
// one block (128 threads, float4 lanes) per dst node
// ---------------------------------------------------------------------------
__global__ __launch_bounds__(128) void aggregate_kernel(const float* __restrict__ h,
                                                        const float* __restrict__ bias,
                                                        float* __restrict__ out,
                                                        int do_relu) {
    int i = blockIdx.x;
    int t = threadIdx.x;           // 0..127, handles 4 floats
    int r0 = g_rowptr[i];
    int r1 = g_rowptr[i + 1];

    float4 acc = make_float4(0.f, 0.f, 0.f, 0.f);
    int e = r0;
    // unroll-by-2 for a little MLP
    for (; e + 1 < r1; e += 2) {
        int   s0 = g_csr_src[e],     s1 = g_csr_src[e + 1];
        float w0 = g_csr_norm[e],    w1 = g_csr_norm[e + 1];
        float4 v0 = *(const float4*)&h[(size_t)s0 * DH + t * 4];
        float4 v1 = *(const float4*)&h[(size_t)s1 * DH + t * 4];
        acc.x += w0 * v0.x + w1 * v1.x;
        acc.y += w0 * v0.y + w1 * v1.y;
        acc.z += w0 * v0.z + w1 * v1.z;
        acc.w += w0 * v0.w + w1 * v1.w;
    }
    if (e < r1) {
        int   s = g_csr_src[e];
        float w = g_csr_norm[e];
        float4 v = *(const float4*)&h[(size_t)s * DH + t * 4];
        acc.x += w * v.x; acc.y += w * v.y; acc.z += w * v.z; acc.w += w * v.w;
    }

    float d = g_dinv[i];
    float w2 = d * d;
    float4 vs = *(const float4*)&h[(size_t)i * DH + t * 4];
    float4 b4 = *(const float4*)&bias[t * 4];
    acc.x += w2 * vs.x + b4.x;
    acc.y += w2 * vs.y + b4.y;
    acc.z += w2 * vs.z + b4.z;
    acc.w += w2 * vs.w + b4.w;
    if (do_relu) {
        acc.x = fmaxf(acc.x, 0.f); acc.y = fmaxf(acc.y, 0.f);
        acc.z = fmaxf(acc.z, 0.f); acc.w = fmaxf(acc.w, 0.f);
    }
    *(float4*)&out[(size_t)i * DH + t * 4] = acc;
}

// ---------------------------------------------------------------------------
// Mean pool per graph (batch is sorted -> binary search the node range)
// ---------------------------------------------------------------------------
__global__ __launch_bounds__(128) void pool_kernel(const float* __restrict__ h,
                                                   const int* __restrict__ batch,
                                                   int enc) {
    int g = blockIdx.x;
    int t = threadIdx.x;

    int lo = 0, hi = NN;
    while (lo < hi) { int m = (lo + hi) >> 1; if (batch[m] < g) lo = m + 1; else hi = m; }
    int start = lo;
    lo = start; hi = NN;
    while (lo < hi) { int m = (lo + hi) >> 1; if (batch[m] < g + 1) lo = m + 1; else hi = m; }
    int end = lo;

    float4 acc = make_float4(0.f, 0.f, 0.f, 0.f);
    for (int r = start; r < end; r++) {
        float4 v = *(const float4*)&h[(size_t)r * DH + t * 4];
        acc.x += v.x; acc.y += v.y; acc.z += v.z; acc.w += v.w;
    }
    float inv = 1.0f / fmaxf((float)(end - start), 1.0f);
    acc.x *= inv; acc.y *= inv; acc.z *= inv; acc.w *= inv;
    *(float4*)&g_pooled[enc][g * DH + t * 4] = acc;
}

// ---------------------------------------------------------------------------
// Final pairwise distance: out[g] = || pooled_a[g] - pooled_b[g] + 1e-6 ||_2
// ---------------------------------------------------------------------------
__global__ __launch_bounds__(128) void dist_kernel(float* __restrict__ out) {
    int g = blockIdx.x;
    int t = threadIdx.x;
    const float* pa = &g_pooled[0][g * DH];
    const float* pb = &g_pooled[1][g * DH];
    float4 a = *(const float4*)&pa[t * 4];
    float4 b = *(const float4*)&pb[t * 4];
    float dx = a.x - b.x + 1e-6f;
    float dy = a.y - b.y + 1e-6f;
    float dz = a.z - b.z + 1e-6f;
    float dw = a.w - b.w + 1e-6f;
    float s = dx * dx + dy * dy + dz * dz + dw * dw;

    __shared__ float red[128];
    red[t] = s;
    __syncthreads();
    for (int off = 64; off > 0; off >>= 1) {
        if (t < off) red[t] += red[t + off];
        __syncthreads();
    }
    if (t == 0) out[g] = sqrtf(red[0]);
}

// ---------------------------------------------------------------------------
// launch
// ---------------------------------------------------------------------------
extern "C" void kernel_launch(void* const* d_in, const int* in_sizes, int n_in,
                              void* d_out, int out_size) {
    const float* x_a     = (const float*)d_in[0];
    const int*   ei_a    = (const int*)  d_in[1];
    const int*   batch_a = (const int*)  d_in[2];
    const float* x_b     = (const float*)d_in[3];
    const int*   ei_b    = (const int*)  d_in[4];
    const int*   batch_b = (const int*)  d_in[5];
    const float* W1 = (const float*)d_in[6];
    const float* b1 = (const float*)d_in[7];
    const float* W2 = (const float*)d_in[8];
    const float* b2 = (const float*)d_in[9];
    const float* W3 = (const float*)d_in[10];
    const float* b3 = (const float*)d_in[11];
    float* out = (float*)d_out;

    const dim3 gemm_grid(DH / 128, (NN + 127) / 128);   // (4, 157)
    const int  eblocks = (EE + 255) / 256;
    const int  nblocks = (NN + 255) / 256;

    for (int enc = 0; enc < 2; enc++) {
        const float* x   = enc ? x_b : x_a;
        const int*   ei  = enc ? ei_b : ei_a;
        const int*   bat = enc ? batch_b : batch_a;
        const int* src = ei;
        const int* dst = ei + EE;

        // CSR build
        zero_deg_kernel<<<nblocks, 256>>>();
        count_deg_kernel<<<eblocks, 256>>>(dst);
        dinv_kernel<<<nblocks, 256>>>();
        scan_kernel<<<1, 1024>>>();
        fill_csr_kernel<<<eblocks, 256>>>(src, dst);

        // layer 1
        sgemm_kernel<<<gemm_grid, 256>>>(x, W1, g_gemm, NN);
        aggregate_kernel<<<NN, 128>>>(g_gemm, b1, g_x, 1);
        // layer 2
        sgemm_kernel<<<gemm_grid, 256>>>(g_x, W2, g_gemm, NN);
        aggregate_kernel<<<NN, 128>>>(g_gemm, b2, g_x, 1);
        // layer 3
        sgemm_kernel<<<gemm_grid, 256>>>(g_x, W3, g_gemm, NN);
        aggregate_kernel<<<NN, 128>>>(g_gemm, b3, g_x, 0);

        // mean pool
        pool_kernel<<<GG, 128>>>(g_x, bat, enc);
    }

    dist_kernel<<<GG, 128>>>(out);
}